// round 1
// baseline (speedup 1.0000x reference)
#include <cuda_runtime.h>
#include <math.h>

#define BSZ 512
#define ZD  256
#define REC_BLOCKS 1024
#define LOG2PI_F 1.8378770664093453f

// ---------------- scratch (device globals; no allocation allowed) ----------
__device__ float g_w[BSZ * ZD];     // exp(logvar)
__device__ float g_a[BSZ * ZD];     // mu * exp(logvar)
__device__ float g_c[BSZ * ZD];     // -0.5*(mu^2*w + logvar + log2pi)
__device__ float g_Crow[BSZ];       // sum_k c[j,k]
__device__ float g_dwkl[BSZ];       // per-row dw_kl sum
__device__ float g_recb[REC_BLOCKS];
__device__ float g_logqz[BSZ];
__device__ float g_pm[BSZ];
__device__ float g_log_norm;

// ---------------- reduction helpers ---------------------------------------
__device__ __forceinline__ float warp_sum(float v) {
#pragma unroll
    for (int o = 16; o; o >>= 1) v += __shfl_xor_sync(0xffffffffu, v, o);
    return v;
}
__device__ __forceinline__ float warp_max(float v) {
#pragma unroll
    for (int o = 16; o; o >>= 1) v = fmaxf(v, __shfl_xor_sync(0xffffffffu, v, o));
    return v;
}

// block of 256 threads; result valid in thread 0
__device__ __forceinline__ float block_sum_256(float v, float* sh) {
    int lane = threadIdx.x & 31, w = threadIdx.x >> 5;
    v = warp_sum(v);
    if (lane == 0) sh[w] = v;
    __syncthreads();
    float r = (threadIdx.x < 8) ? sh[threadIdx.x] : 0.0f;
    if (w == 0) r = warp_sum(r);
    __syncthreads();
    return r;
}
__device__ __forceinline__ float block_max_256(float v, float* sh) {
    int lane = threadIdx.x & 31, w = threadIdx.x >> 5;
    v = warp_max(v);
    if (lane == 0) sh[w] = v;
    __syncthreads();
    float r = (threadIdx.x < 8) ? sh[threadIdx.x] : -INFINITY;
    if (w == 0) r = warp_max(r);
    __syncthreads();
    return r;
}

// ---------------- kernel 1: precompute w/a/c, row sums, dw_kl, log_norm ----
__global__ void __launch_bounds__(256) prep_kernel(const float* __restrict__ mu,
                                                   const float* __restrict__ logvar,
                                                   const void* __restrict__ dsz) {
    __shared__ float sh[8];
    __shared__ float sh2[8];
    int j = blockIdx.x;
    int k = threadIdx.x;
    int idx = j * ZD + k;

    float lv = logvar[idx];
    float m  = mu[idx];
    float w  = __expf(lv);
    float a  = m * w;
    float c  = -0.5f * (fmaf(m * m, w, lv) + LOG2PI_F);
    g_w[idx] = w;
    g_a[idx] = a;
    g_c[idx] = c;

    // dw_kl term: -0.5*lv + 0.5*exp(lv + mu^2) - 0.5
    float dw = fmaf(0.5f, __expf(lv + m * m), fmaf(-0.5f, lv, -0.5f));

    // two block sums (separate smem buffers, one sync pattern each)
    int lane = threadIdx.x & 31, wp = threadIdx.x >> 5;
    float cs = warp_sum(c);
    float ds = warp_sum(dw);
    if (lane == 0) { sh[wp] = cs; sh2[wp] = ds; }
    __syncthreads();
    if (threadIdx.x == 0) {
        float ct = 0.0f, dt = 0.0f;
#pragma unroll
        for (int q = 0; q < 8; q++) { ct += sh[q]; dt += sh2[q]; }
        g_Crow[j] = ct;
        g_dwkl[j] = dt;
    }

    if (j == 0 && threadIdx.x == 0) {
        // dataset_size may arrive as int32/int64 or float32; disambiguate.
        int   iv = ((const int*)dsz)[0];
        float fv = ((const float*)dsz)[0];
        float ds_val = (iv > 0 && iv < 1073741824) ? (float)iv : fv;
        g_log_norm = logf((float)BSZ) + logf(ds_val);
    }
}

// ---------------- kernel 2: bernoulli BCE reduction -------------------------
__global__ void __launch_bounds__(256) rec_kernel(const float* __restrict__ data,
                                                  const float* __restrict__ recon,
                                                  int n) {
    __shared__ float sh[8];
    float acc = 0.0f;
    for (int i = blockIdx.x * blockDim.x + threadIdx.x; i < n;
         i += gridDim.x * blockDim.x) {
        float d = data[i];
        float r = recon[i];
        acc += d * __logf(r) + (1.0f - d) * __logf(1.0f - r);
    }
    float s = block_sum_256(acc, sh);
    if (threadIdx.x == 0) g_recb[blockIdx.x] = s;
}

// ---------------- kernel 3: logqz[i] = lse_j( sum_k f(i,j,k) ) - log_norm ---
// One block per i. Warp per j (8 warps stride over 512 j), lanes over k.
__global__ void __launch_bounds__(256) logqz_kernel(const float* __restrict__ lat) {
    __shared__ float sM[BSZ];
    __shared__ float sh[8];
    int i = blockIdx.x;
    int t = threadIdx.x, lane = t & 31, wp = t >> 5;

    // each lane owns 8 k-values: k = lane + 32*q
    float sq[8], hq[8];
#pragma unroll
    for (int q = 0; q < 8; q++) {
        float v = lat[i * ZD + lane + 32 * q];
        sq[q] = v;
        hq[q] = -0.5f * v * v;
    }

    for (int j = wp; j < BSZ; j += 8) {
        const float* wr = g_w + j * ZD;
        const float* ar = g_a + j * ZD;
        float p = 0.0f;
#pragma unroll
        for (int q = 0; q < 8; q++) {
            int k = lane + 32 * q;
            p = fmaf(hq[q], wr[k], p);
            p = fmaf(sq[q], ar[k], p);
        }
        p = warp_sum(p);
        if (lane == 0) sM[j] = p + g_Crow[j];
    }
    __syncthreads();

    // logsumexp over 512 row-sums
    float mx = -INFINITY;
#pragma unroll
    for (int j = t; j < BSZ; j += 256) mx = fmaxf(mx, sM[j]);
    mx = block_max_256(mx, sh);
    __shared__ float s_mx;
    if (t == 0) s_mx = mx;
    __syncthreads();
    mx = s_mx;

    float se = 0.0f;
#pragma unroll
    for (int j = t; j < BSZ; j += 256) se += __expf(sM[j] - mx);
    se = block_sum_256(se, sh);
    if (t == 0) g_logqz[i] = mx + __logf(se) - g_log_norm;
}

// ---------------- kernel 4: prodmarginals ----------------------------------
// One block per i, thread t owns k=t. Two passes over j (max, then sum-exp).
__global__ void __launch_bounds__(256) pm_kernel(const float* __restrict__ lat) {
    __shared__ float sh[8];
    int i = blockIdx.x;
    int t = threadIdx.x;

    float s = lat[i * ZD + t];
    float h = -0.5f * s * s;

    const float* wp = g_w + t;
    const float* ap = g_a + t;
    const float* cp = g_c + t;

    float mx0 = -INFINITY, mx1 = -INFINITY;
#pragma unroll 4
    for (int j = 0; j < BSZ; j += 2) {
        float f0 = fmaf(h, wp[j * ZD],       fmaf(s, ap[j * ZD],       cp[j * ZD]));
        float f1 = fmaf(h, wp[(j + 1) * ZD], fmaf(s, ap[(j + 1) * ZD], cp[(j + 1) * ZD]));
        mx0 = fmaxf(mx0, f0);
        mx1 = fmaxf(mx1, f1);
    }
    float mx = fmaxf(mx0, mx1);

    float se0 = 0.0f, se1 = 0.0f;
#pragma unroll 4
    for (int j = 0; j < BSZ; j += 2) {
        float f0 = fmaf(h, wp[j * ZD],       fmaf(s, ap[j * ZD],       cp[j * ZD]));
        float f1 = fmaf(h, wp[(j + 1) * ZD], fmaf(s, ap[(j + 1) * ZD], cp[(j + 1) * ZD]));
        se0 += __expf(f0 - mx);
        se1 += __expf(f1 - mx);
    }
    float v = mx + __logf(se0 + se1);

    float tot = block_sum_256(v, sh);
    if (t == 0) g_pm[i] = tot - (float)ZD * g_log_norm;
}

// ---------------- kernel 5: finalize ---------------------------------------
__global__ void __launch_bounds__(256) final_kernel(float* __restrict__ out) {
    __shared__ float sh[8];
    int t = threadIdx.x;

    float rec = 0.0f;
    for (int b = t; b < REC_BLOCKS; b += 256) rec += g_recb[b];
    float dw = 0.0f, tc = 0.0f;
    for (int b = t; b < BSZ; b += 256) {
        dw += g_dwkl[b];
        tc += g_logqz[b] - g_pm[b];
    }

    rec = block_sum_256(rec, sh);
    dw  = block_sum_256(dw,  sh);
    tc  = block_sum_256(tc,  sh);

    if (t == 0) {
        // elbo = (-rec_sum + tc_sum + dw_sum) / 512
        out[0] = (tc + dw - rec) * (1.0f / (float)BSZ);
    }
}

// ---------------- launch ----------------------------------------------------
extern "C" void kernel_launch(void* const* d_in, const int* in_sizes, int n_in,
                              void* d_out, int out_size) {
    const float* data   = (const float*)d_in[0];
    const float* recon  = (const float*)d_in[1];
    const float* latent = (const float*)d_in[2];
    const float* mu     = (const float*)d_in[3];
    const float* logvar = (const float*)d_in[4];
    const void*  dsz    = d_in[5];

    int npix = in_sizes[0];

    prep_kernel<<<BSZ, 256>>>(mu, logvar, dsz);
    rec_kernel<<<REC_BLOCKS, 256>>>(data, recon, npix);
    logqz_kernel<<<BSZ, 256>>>(latent);
    pm_kernel<<<BSZ, 256>>>(latent);
    final_kernel<<<1, 256>>>((float*)d_out);
}

// round 2
// speedup vs baseline: 1.3407x; 1.3407x over previous
#include <cuda_runtime.h>
#include <math.h>

#define BSZ 512
#define ZD  256
#define REC_BLOCKS 1024
#define TI 8            // i-values per pm block
#define JCHUNKS 8       // j-chunks
#define JC (BSZ / JCHUNKS)
#define LOG2PI_F 1.8378770664093453f
#define LOG2E_F  1.4426950408889634f

// ---------------- scratch (device globals; no allocation allowed) ----------
__device__ float g_w[BSZ * ZD];      // exp(logvar)                (logqz)
__device__ float g_a[BSZ * ZD];      // mu * exp(logvar)           (logqz)
__device__ float g_w2[BSZ * ZD];     // w * log2e                  (pm)
__device__ float g_a2[BSZ * ZD];     // a * log2e                  (pm)
__device__ float g_c2[BSZ * ZD];     // c * log2e                  (pm)
__device__ float g_Crow[BSZ];        // sum_k c[j,k]
__device__ float g_dwkl[BSZ];
__device__ float g_recb[REC_BLOCKS];
__device__ float g_logqz[BSZ];
__device__ float g_pm[BSZ];
__device__ float g_log_norm;
__device__ float g_S[JCHUNKS][BSZ * ZD];   // pm partial sums (4MB)

// ---------------- helpers ---------------------------------------------------
__device__ __forceinline__ float warp_sum(float v) {
#pragma unroll
    for (int o = 16; o; o >>= 1) v += __shfl_xor_sync(0xffffffffu, v, o);
    return v;
}
__device__ __forceinline__ float warp_max(float v) {
#pragma unroll
    for (int o = 16; o; o >>= 1) v = fmaxf(v, __shfl_xor_sync(0xffffffffu, v, o));
    return v;
}
__device__ __forceinline__ float block_sum_256(float v, float* sh) {
    int lane = threadIdx.x & 31, w = threadIdx.x >> 5;
    v = warp_sum(v);
    if (lane == 0) sh[w] = v;
    __syncthreads();
    float r = (threadIdx.x < 8) ? sh[threadIdx.x] : 0.0f;
    if (w == 0) r = warp_sum(r);
    __syncthreads();
    return r;
}
__device__ __forceinline__ float block_max_256(float v, float* sh) {
    int lane = threadIdx.x & 31, w = threadIdx.x >> 5;
    v = warp_max(v);
    if (lane == 0) sh[w] = v;
    __syncthreads();
    float r = (threadIdx.x < 8) ? sh[threadIdx.x] : -INFINITY;
    if (w == 0) r = warp_max(r);
    __syncthreads();
    return r;
}

// Fast exp2 on the FMA/ALU pipes (no MUFU). x must be <= ~0; clamped at -120.
// Magic-constant round-to-int, degree-5 poly for 2^r on r in [-0.5, 0.5],
// exponent injected via integer add. Rel err ~2.4e-6.
__device__ __forceinline__ float fast_exp2(float x) {
    x = fmaxf(x, -120.0f);
    float t = x + 12582912.0f;                 // 2^23 + 2^22
    int   nb = __float_as_int(t) << 23;        // == n << 23 (mod 2^32)
    float r = x - (t - 12582912.0f);           // r in [-0.5, 0.5]
    float p = 0.0013333558f;
    p = fmaf(p, r, 0.0096181291f);
    p = fmaf(p, r, 0.055504110f);
    p = fmaf(p, r, 0.24022650f);
    p = fmaf(p, r, 0.69314718f);
    p = fmaf(p, r, 1.0f);
    return __int_as_float(__float_as_int(p) + nb);
}

// ---------------- kernel 1: precompute --------------------------------------
__global__ void __launch_bounds__(256) prep_kernel(const float* __restrict__ mu,
                                                   const float* __restrict__ logvar,
                                                   const void* __restrict__ dsz) {
    __shared__ float sh[8];
    __shared__ float sh2[8];
    int j = blockIdx.x;
    int idx = j * ZD + threadIdx.x;

    float lv = logvar[idx];
    float m  = mu[idx];
    float w  = __expf(lv);
    float a  = m * w;
    float c  = -0.5f * (fmaf(m * m, w, lv) + LOG2PI_F);
    g_w[idx]  = w;
    g_a[idx]  = a;
    g_w2[idx] = w * LOG2E_F;
    g_a2[idx] = a * LOG2E_F;
    g_c2[idx] = c * LOG2E_F;

    float dw = fmaf(0.5f, __expf(lv + m * m), fmaf(-0.5f, lv, -0.5f));

    int lane = threadIdx.x & 31, wp = threadIdx.x >> 5;
    float cs = warp_sum(c);
    float ds = warp_sum(dw);
    if (lane == 0) { sh[wp] = cs; sh2[wp] = ds; }
    __syncthreads();
    if (threadIdx.x == 0) {
        float ct = 0.0f, dt = 0.0f;
#pragma unroll
        for (int q = 0; q < 8; q++) { ct += sh[q]; dt += sh2[q]; }
        g_Crow[j] = ct;
        g_dwkl[j] = dt;
    }

    if (j == 0 && threadIdx.x == 0) {
        int   iv = ((const int*)dsz)[0];
        float fv = ((const float*)dsz)[0];
        float ds_val = (iv > 0 && iv < 1073741824) ? (float)iv : fv;
        g_log_norm = logf((float)BSZ) + logf(ds_val);
    }
}

// ---------------- kernel 2: bernoulli BCE reduction --------------------------
__global__ void __launch_bounds__(256) rec_kernel(const float* __restrict__ data,
                                                  const float* __restrict__ recon,
                                                  int n) {
    __shared__ float sh[8];
    float acc = 0.0f;
    for (int i = blockIdx.x * blockDim.x + threadIdx.x; i < n;
         i += gridDim.x * blockDim.x) {
        float d = data[i];
        float r = recon[i];
        acc += d * __logf(r) + (1.0f - d) * __logf(1.0f - r);
    }
    float s = block_sum_256(acc, sh);
    if (threadIdx.x == 0) g_recb[blockIdx.x] = s;
}

// ---------------- kernel 3: logqz[i] = lse_j( sum_k f(i,j,k) ) ---------------
__global__ void __launch_bounds__(256) logqz_kernel(const float* __restrict__ lat) {
    __shared__ float sM[BSZ];
    __shared__ float sh[8];
    int i = blockIdx.x;
    int t = threadIdx.x, lane = t & 31, wp = t >> 5;

    float sq[8], hq[8];
#pragma unroll
    for (int q = 0; q < 8; q++) {
        float v = lat[i * ZD + lane + 32 * q];
        sq[q] = v;
        hq[q] = -0.5f * v * v;
    }

    for (int j = wp; j < BSZ; j += 8) {
        const float* wr = g_w + j * ZD;
        const float* ar = g_a + j * ZD;
        float p = 0.0f;
#pragma unroll
        for (int q = 0; q < 8; q++) {
            int k = lane + 32 * q;
            p = fmaf(hq[q], wr[k], p);
            p = fmaf(sq[q], ar[k], p);
        }
        p = warp_sum(p);
        if (lane == 0) sM[j] = p + g_Crow[j];
    }
    __syncthreads();

    float mx = -INFINITY;
#pragma unroll
    for (int j = t; j < BSZ; j += 256) mx = fmaxf(mx, sM[j]);
    mx = block_max_256(mx, sh);
    __shared__ float s_mx;
    if (t == 0) s_mx = mx;
    __syncthreads();
    mx = s_mx;

    float se = 0.0f;
#pragma unroll
    for (int j = t; j < BSZ; j += 256) se += __expf(sM[j] - mx);
    se = block_sum_256(se, sh);
    if (t == 0) g_logqz[i] = mx + __logf(se) - g_log_norm;
}

// ---------------- kernel 4: pm partial sums ----------------------------------
// grid (BSZ/TI, JCHUNKS), block 256. Thread t owns k=t for TI i-values.
// Single pass (no max shift needed: f <= -0.66, exp(f) in fp32 range).
__global__ void __launch_bounds__(256) pm_partial_kernel(const float* __restrict__ lat) {
    int i0 = blockIdx.x * TI;
    int jc = blockIdx.y;
    int t  = threadIdx.x;

    float s[TI], h[TI], acc[TI];
#pragma unroll
    for (int ii = 0; ii < TI; ii++) {
        float v = lat[(i0 + ii) * ZD + t];
        s[ii] = v * LOG2E_F;        // pre-scale: f*log2e = h*w2 + s*a2 + c2
        h[ii] = -0.5f * v * v;      // pairs with w2 (already log2e-scaled)
        acc[ii] = 0.0f;
    }

    const float* wp = g_w2 + jc * JC * ZD + t;
    const float* ap = g_a2 + jc * JC * ZD + t;
    const float* cp = g_c2 + jc * JC * ZD + t;

#pragma unroll 2
    for (int j = 0; j < JC; j++) {
        float w = wp[j * ZD];
        float a = ap[j * ZD];
        float c = cp[j * ZD];
#pragma unroll
        for (int ii = 0; ii < TI; ii++) {
            float x = fmaf(h[ii], w, fmaf(s[ii], a, c));
            acc[ii] += fast_exp2(x);
        }
    }

#pragma unroll
    for (int ii = 0; ii < TI; ii++)
        g_S[jc][(i0 + ii) * ZD + t] = acc[ii];
}

// ---------------- kernel 5: pm finalize: sum_k log(sum over chunks) ----------
__global__ void __launch_bounds__(256) pm_log_kernel() {
    __shared__ float sh[8];
    int i = blockIdx.x;
    int t = threadIdx.x;
    int idx = i * ZD + t;

    float S = 0.0f;
#pragma unroll
    for (int jc = 0; jc < JCHUNKS; jc++) S += g_S[jc][idx];
    float v = __logf(S);

    float tot = block_sum_256(v, sh);
    if (t == 0) g_pm[i] = tot - (float)ZD * g_log_norm;
}

// ---------------- kernel 6: finalize -----------------------------------------
__global__ void __launch_bounds__(256) final_kernel(float* __restrict__ out) {
    __shared__ float sh[8];
    int t = threadIdx.x;

    float rec = 0.0f;
    for (int b = t; b < REC_BLOCKS; b += 256) rec += g_recb[b];
    float dw = 0.0f, tc = 0.0f;
    for (int b = t; b < BSZ; b += 256) {
        dw += g_dwkl[b];
        tc += g_logqz[b] - g_pm[b];
    }

    rec = block_sum_256(rec, sh);
    dw  = block_sum_256(dw,  sh);
    tc  = block_sum_256(tc,  sh);

    if (t == 0) out[0] = (tc + dw - rec) * (1.0f / (float)BSZ);
}

// ---------------- launch ------------------------------------------------------
extern "C" void kernel_launch(void* const* d_in, const int* in_sizes, int n_in,
                              void* d_out, int out_size) {
    const float* data   = (const float*)d_in[0];
    const float* recon  = (const float*)d_in[1];
    const float* latent = (const float*)d_in[2];
    const float* mu     = (const float*)d_in[3];
    const float* logvar = (const float*)d_in[4];
    const void*  dsz    = d_in[5];

    int npix = in_sizes[0];

    prep_kernel<<<BSZ, 256>>>(mu, logvar, dsz);
    rec_kernel<<<REC_BLOCKS, 256>>>(data, recon, npix);
    logqz_kernel<<<BSZ, 256>>>(latent);
    dim3 pmgrid(BSZ / TI, JCHUNKS);
    pm_partial_kernel<<<pmgrid, 256>>>(latent);
    pm_log_kernel<<<BSZ, 256>>>();
    final_kernel<<<1, 256>>>((float*)d_out);
}

// round 3
// speedup vs baseline: 2.0449x; 1.5252x over previous
#include <cuda_runtime.h>
#include <math.h>
#include <stdint.h>

#define BSZ 512
#define ZD  256
#define KK2 512                 // concat K for GEMM (h|s vs w|a)
#define REC_BLOCKS 1024
#define TI 8                    // i-values per pm block
#define JCHUNKS 8
#define JC (BSZ / JCHUNKS)
#define GBM 64
#define GBN 64
#define GBK 32
#define LOG2PI_F 1.8378770664093453f
#define LOG2E_F  1.4426950408889634f

typedef unsigned long long u64;

// ---------------- scratch ----------------------------------------------------
__device__ float g_wa[BSZ * KK2];     // [j][0:256)=w=exp(lv), [256:512)=a=mu*w
__device__ float g_hs[BSZ * KK2];     // [i][0:256)=-0.5*lat^2, [256:512)=lat
__device__ float g_w2[BSZ * ZD];      // w * log2e    (pm)
__device__ float g_a2[BSZ * ZD];      // a * log2e    (pm)
__device__ float g_c2[BSZ * ZD];      // c * log2e    (pm)
__device__ float g_Crow[BSZ];
__device__ float g_dwkl[BSZ];
__device__ float g_recb[REC_BLOCKS];
__device__ float g_logqz[BSZ];
__device__ float g_pm[BSZ];
__device__ float g_log_norm;
__device__ float g_M[2][BSZ * BSZ];          // GEMM split-K partials (2MB)
__device__ float g_S[JCHUNKS][BSZ * ZD];     // pm partial sums (4MB)

// ---------------- packed f32x2 helpers ---------------------------------------
__device__ __forceinline__ u64 pk2(float lo, float hi) {
    u64 r; asm("mov.b64 %0,{%1,%2};" : "=l"(r) : "f"(lo), "f"(hi)); return r;
}
__device__ __forceinline__ void upk2(u64 v, float& lo, float& hi) {
    asm("mov.b64 {%0,%1},%2;" : "=f"(lo), "=f"(hi) : "l"(v));
}
__device__ __forceinline__ u64 fma2(u64 a, u64 b, u64 c) {
    u64 d; asm("fma.rn.f32x2 %0,%1,%2,%3;" : "=l"(d) : "l"(a), "l"(b), "l"(c)); return d;
}
__device__ __forceinline__ u64 add2(u64 a, u64 b) {
    u64 d; asm("add.rn.f32x2 %0,%1,%2;" : "=l"(d) : "l"(a), "l"(b)); return d;
}
__device__ __forceinline__ u64 mul2(u64 a, u64 b) {
    u64 d; asm("mul.rn.f32x2 %0,%1,%2;" : "=l"(d) : "l"(a), "l"(b)); return d;
}

// ---------------- reductions --------------------------------------------------
__device__ __forceinline__ float warp_sum(float v) {
#pragma unroll
    for (int o = 16; o; o >>= 1) v += __shfl_xor_sync(0xffffffffu, v, o);
    return v;
}
__device__ __forceinline__ float warp_max(float v) {
#pragma unroll
    for (int o = 16; o; o >>= 1) v = fmaxf(v, __shfl_xor_sync(0xffffffffu, v, o));
    return v;
}
__device__ __forceinline__ float block_sum_256(float v, float* sh) {
    int lane = threadIdx.x & 31, w = threadIdx.x >> 5;
    v = warp_sum(v);
    if (lane == 0) sh[w] = v;
    __syncthreads();
    float r = (threadIdx.x < 8) ? sh[threadIdx.x] : 0.0f;
    if (w == 0) r = warp_sum(r);
    __syncthreads();
    return r;
}
__device__ __forceinline__ float block_max_256(float v, float* sh) {
    int lane = threadIdx.x & 31, w = threadIdx.x >> 5;
    v = warp_max(v);
    if (lane == 0) sh[w] = v;
    __syncthreads();
    float r = (threadIdx.x < 8) ? sh[threadIdx.x] : -INFINITY;
    if (w == 0) r = warp_max(r);
    __syncthreads();
    return r;
}

// ---------------- FMA-pipe natural log (Cephes-style, ~1e-7 rel) --------------
__device__ __forceinline__ float fast_log(float x) {
    int ix = __float_as_int(x);
    int e  = (ix - 0x3f3504f3) >> 23;            // m in [sqrt(.5), sqrt(2))
    float m = __int_as_float(ix - (e << 23));
    float f = m - 1.0f;
    float z = f * f;
    float y = 7.0376836292e-2f;
    y = fmaf(y, f, -1.1514610310e-1f);
    y = fmaf(y, f,  1.1676998740e-1f);
    y = fmaf(y, f, -1.2420140846e-1f);
    y = fmaf(y, f,  1.4249322787e-1f);
    y = fmaf(y, f, -1.6668057665e-1f);
    y = fmaf(y, f,  2.0000714765e-1f);
    y = fmaf(y, f, -2.4999993993e-1f);
    y = fmaf(y, f,  3.3333331174e-1f);
    y = y * f * z;
    float ef = (float)e;
    y = fmaf(ef, -2.12194440e-4f, y);
    y = fmaf(-0.5f, z, y);
    float r = f + y;
    return fmaf(ef, 0.693359375f, r);
}

// ---------------- kernel 1: precompute ----------------------------------------
__global__ void __launch_bounds__(256) prep_kernel(const float* __restrict__ mu,
                                                   const float* __restrict__ logvar,
                                                   const void* __restrict__ dsz) {
    __shared__ float sh[8];
    __shared__ float sh2[8];
    int j = blockIdx.x;
    int t = threadIdx.x;
    int idx = j * ZD + t;

    float lv = logvar[idx];
    float m  = mu[idx];
    float w  = __expf(lv);
    float a  = m * w;
    float c  = -0.5f * (fmaf(m * m, w, lv) + LOG2PI_F);
    g_wa[j * KK2 + t]      = w;
    g_wa[j * KK2 + ZD + t] = a;
    g_w2[idx] = w * LOG2E_F;
    g_a2[idx] = a * LOG2E_F;
    g_c2[idx] = c * LOG2E_F;

    float dw = fmaf(0.5f, __expf(lv + m * m), fmaf(-0.5f, lv, -0.5f));

    int lane = t & 31, wp = t >> 5;
    float cs = warp_sum(c);
    float ds = warp_sum(dw);
    if (lane == 0) { sh[wp] = cs; sh2[wp] = ds; }
    __syncthreads();
    if (t == 0) {
        float ct = 0.0f, dt = 0.0f;
#pragma unroll
        for (int q = 0; q < 8; q++) { ct += sh[q]; dt += sh2[q]; }
        g_Crow[j] = ct;
        g_dwkl[j] = dt;
    }

    if (j == 0 && t == 0) {
        int   iv = ((const int*)dsz)[0];
        float fv = ((const float*)dsz)[0];
        float ds_val = (iv > 0 && iv < 1073741824) ? (float)iv : fv;
        g_log_norm = logf((float)BSZ) + logf(ds_val);
    }
}

// ---------------- kernel 1b: latent features for GEMM --------------------------
__global__ void __launch_bounds__(256) lat_prep_kernel(const float* __restrict__ lat) {
    int i = blockIdx.x, t = threadIdx.x;
    float v = lat[i * ZD + t];
    g_hs[i * KK2 + t]      = -0.5f * v * v;
    g_hs[i * KK2 + ZD + t] = v;
}

// ---------------- kernel 2: BCE reduction (FMA-pipe log, float4) ---------------
__global__ void __launch_bounds__(256) rec_kernel(const float* __restrict__ data,
                                                  const float* __restrict__ recon,
                                                  int n4) {
    __shared__ float sh[8];
    const float4* d4 = (const float4*)data;
    const float4* r4 = (const float4*)recon;
    float acc = 0.0f;
    for (int i = blockIdx.x * blockDim.x + threadIdx.x; i < n4;
         i += gridDim.x * blockDim.x) {
        float4 d = d4[i];
        float4 r = r4[i];
        acc += d.x * fast_log(r.x) + (1.0f - d.x) * fast_log(1.0f - r.x);
        acc += d.y * fast_log(r.y) + (1.0f - d.y) * fast_log(1.0f - r.y);
        acc += d.z * fast_log(r.z) + (1.0f - d.z) * fast_log(1.0f - r.z);
        acc += d.w * fast_log(r.w) + (1.0f - d.w) * fast_log(1.0f - r.w);
    }
    float s = block_sum_256(acc, sh);
    if (threadIdx.x == 0) g_recb[blockIdx.x] = s;
}

// ---------------- kernel 3a: row-sum matrix via tiled GEMM ---------------------
// M_split[z][i][j] = sum_{k in split z} g_hs[i][k] * g_wa[j][k]
__global__ void __launch_bounds__(256) gemm_kernel() {
    __shared__ float As[GBK * 65];
    __shared__ float Bs[GBK * 65];
    int tid = threadIdx.x;
    int j0 = blockIdx.x * GBN;
    int i0 = blockIdx.y * GBM;
    int kb = blockIdx.z * (KK2 / 2);
    int tx = tid & 15, ty = tid >> 4;

    float acc[4][4];
#pragma unroll
    for (int r = 0; r < 4; r++)
#pragma unroll
        for (int c = 0; c < 4; c++) acc[r][c] = 0.0f;

    for (int kc = 0; kc < KK2 / 2; kc += GBK) {
#pragma unroll
        for (int p = 0; p < 2; p++) {
            int q   = tid + p * 256;
            int row = q >> 3;
            int k4  = (q & 7) * 4;
            float4 va = *(const float4*)&g_hs[(i0 + row) * KK2 + kb + kc + k4];
            float4 vb = *(const float4*)&g_wa[(j0 + row) * KK2 + kb + kc + k4];
            As[(k4 + 0) * 65 + row] = va.x;
            As[(k4 + 1) * 65 + row] = va.y;
            As[(k4 + 2) * 65 + row] = va.z;
            As[(k4 + 3) * 65 + row] = va.w;
            Bs[(k4 + 0) * 65 + row] = vb.x;
            Bs[(k4 + 1) * 65 + row] = vb.y;
            Bs[(k4 + 2) * 65 + row] = vb.z;
            Bs[(k4 + 3) * 65 + row] = vb.w;
        }
        __syncthreads();
#pragma unroll
        for (int kk = 0; kk < GBK; kk++) {
            float a0 = As[kk * 65 + ty * 4 + 0];
            float a1 = As[kk * 65 + ty * 4 + 1];
            float a2 = As[kk * 65 + ty * 4 + 2];
            float a3 = As[kk * 65 + ty * 4 + 3];
            float b0 = Bs[kk * 65 + tx];
            float b1 = Bs[kk * 65 + tx + 16];
            float b2 = Bs[kk * 65 + tx + 32];
            float b3 = Bs[kk * 65 + tx + 48];
            acc[0][0] = fmaf(a0, b0, acc[0][0]); acc[0][1] = fmaf(a0, b1, acc[0][1]);
            acc[0][2] = fmaf(a0, b2, acc[0][2]); acc[0][3] = fmaf(a0, b3, acc[0][3]);
            acc[1][0] = fmaf(a1, b0, acc[1][0]); acc[1][1] = fmaf(a1, b1, acc[1][1]);
            acc[1][2] = fmaf(a1, b2, acc[1][2]); acc[1][3] = fmaf(a1, b3, acc[1][3]);
            acc[2][0] = fmaf(a2, b0, acc[2][0]); acc[2][1] = fmaf(a2, b1, acc[2][1]);
            acc[2][2] = fmaf(a2, b2, acc[2][2]); acc[2][3] = fmaf(a2, b3, acc[2][3]);
            acc[3][0] = fmaf(a3, b0, acc[3][0]); acc[3][1] = fmaf(a3, b1, acc[3][1]);
            acc[3][2] = fmaf(a3, b2, acc[3][2]); acc[3][3] = fmaf(a3, b3, acc[3][3]);
        }
        __syncthreads();
    }

    float* out = g_M[blockIdx.z];
#pragma unroll
    for (int r = 0; r < 4; r++)
#pragma unroll
        for (int c = 0; c < 4; c++)
            out[(i0 + ty * 4 + r) * BSZ + j0 + tx + 16 * c] = acc[r][c];
}

// ---------------- kernel 3b: LSE over rows of M --------------------------------
__global__ void __launch_bounds__(256) lse_kernel() {
    __shared__ float sh[8];
    __shared__ float smx;
    int i = blockIdx.x, t = threadIdx.x;

    float v0 = g_M[0][i * BSZ + t]       + g_M[1][i * BSZ + t]       + g_Crow[t];
    float v1 = g_M[0][i * BSZ + t + 256] + g_M[1][i * BSZ + t + 256] + g_Crow[t + 256];

    float mx = block_max_256(fmaxf(v0, v1), sh);
    if (t == 0) smx = mx;
    __syncthreads();
    mx = smx;

    float se = __expf(v0 - mx) + __expf(v1 - mx);
    se = block_sum_256(se, sh);
    if (t == 0) g_logqz[i] = mx + __logf(se) - g_log_norm;
}

// ---------------- kernel 4: pm partial sums (packed f32x2) ---------------------
__global__ void __launch_bounds__(256) pm_partial_kernel(const float* __restrict__ lat) {
    int i0 = blockIdx.x * TI;
    int jc = blockIdx.y;
    int t  = threadIdx.x;

    u64 s2[TI / 2], h2[TI / 2], acc[TI / 2];
#pragma unroll
    for (int p = 0; p < TI / 2; p++) {
        float v0 = lat[(i0 + 2 * p) * ZD + t];
        float v1 = lat[(i0 + 2 * p + 1) * ZD + t];
        s2[p]  = pk2(v0 * LOG2E_F, v1 * LOG2E_F);
        h2[p]  = pk2(-0.5f * v0 * v0, -0.5f * v1 * v1);
        acc[p] = 0ULL;                          // (0.0f, 0.0f)
    }

    const float* wp = g_w2 + jc * JC * ZD + t;
    const float* ap = g_a2 + jc * JC * ZD + t;
    const float* cp = g_c2 + jc * JC * ZD + t;

    const u64 MAGIC2  = pk2( 12582912.0f,  12582912.0f);
    const u64 NMAGIC2 = pk2(-12582912.0f, -12582912.0f);
    const u64 NEG1    = pk2(-1.0f, -1.0f);
    const u64 C0 = pk2(1.0f, 1.0f);
    const u64 C1 = pk2(0.69314718f,  0.69314718f);
    const u64 C2 = pk2(0.24022650f,  0.24022650f);
    const u64 C3 = pk2(0.055504110f, 0.055504110f);
    const u64 C4 = pk2(0.0096181291f, 0.0096181291f);
    const u64 C5 = pk2(0.0013333558f, 0.0013333558f);

#pragma unroll 4
    for (int j = 0; j < JC; j++) {
        float w = wp[j * ZD];
        float a = ap[j * ZD];
        float c = cp[j * ZD];
        u64 w2 = pk2(w, w), a2 = pk2(a, a), c2 = pk2(c, c);
#pragma unroll
        for (int p = 0; p < TI / 2; p++) {
            u64 x  = fma2(h2[p], w2, fma2(s2[p], a2, c2));  // log2-domain exponent
            u64 tt = add2(x, MAGIC2);                        // round to int (magic)
            u64 tm = add2(tt, NMAGIC2);                      // n as float
            u64 r  = fma2(tm, NEG1, x);                      // r = x - n, in [-.5,.5]
            u64 rr = mul2(r, r);
            u64 A  = fma2(r, C1, C0);
            u64 B  = fma2(r, C3, C2);
            u64 Cc = fma2(r, C5, C4);
            u64 D  = fma2(rr, Cc, B);
            u64 E  = fma2(rr, D, A);                         // 2^r
            int tlo = (int)tt;
            int thi = (int)(tt >> 32);
            float nlo = __int_as_float((tlo << 23) + 0x3F800000);  // 2^n
            float nhi = __int_as_float((thi << 23) + 0x3F800000);
            acc[p] = fma2(E, pk2(nlo, nhi), acc[p]);
        }
    }

#pragma unroll
    for (int p = 0; p < TI / 2; p++) {
        float a0, a1;
        upk2(acc[p], a0, a1);
        g_S[jc][(i0 + 2 * p) * ZD + t]     = a0;
        g_S[jc][(i0 + 2 * p + 1) * ZD + t] = a1;
    }
}

// ---------------- kernel 5: pm finalize -----------------------------------------
__global__ void __launch_bounds__(256) pm_log_kernel() {
    __shared__ float sh[8];
    int i = blockIdx.x;
    int t = threadIdx.x;
    int idx = i * ZD + t;

    float S = 0.0f;
#pragma unroll
    for (int jc = 0; jc < JCHUNKS; jc++) S += g_S[jc][idx];
    float v = fast_log(S);

    float tot = block_sum_256(v, sh);
    if (t == 0) g_pm[i] = tot - (float)ZD * g_log_norm;
}

// ---------------- kernel 6: finalize ---------------------------------------------
__global__ void __launch_bounds__(256) final_kernel(float* __restrict__ out) {
    __shared__ float sh[8];
    int t = threadIdx.x;

    float rec = 0.0f;
    for (int b = t; b < REC_BLOCKS; b += 256) rec += g_recb[b];
    float dw = 0.0f, tc = 0.0f;
    for (int b = t; b < BSZ; b += 256) {
        dw += g_dwkl[b];
        tc += g_logqz[b] - g_pm[b];
    }

    rec = block_sum_256(rec, sh);
    dw  = block_sum_256(dw,  sh);
    tc  = block_sum_256(tc,  sh);

    if (t == 0) out[0] = (tc + dw - rec) * (1.0f / (float)BSZ);
}

// ---------------- launch ----------------------------------------------------------
extern "C" void kernel_launch(void* const* d_in, const int* in_sizes, int n_in,
                              void* d_out, int out_size) {
    const float* data   = (const float*)d_in[0];
    const float* recon  = (const float*)d_in[1];
    const float* latent = (const float*)d_in[2];
    const float* mu     = (const float*)d_in[3];
    const float* logvar = (const float*)d_in[4];
    const void*  dsz    = d_in[5];

    int npix = in_sizes[0];

    prep_kernel<<<BSZ, 256>>>(mu, logvar, dsz);
    lat_prep_kernel<<<BSZ, 256>>>(latent);
    rec_kernel<<<REC_BLOCKS, 256>>>(data, recon, npix / 4);
    gemm_kernel<<<dim3(BSZ / GBN, BSZ / GBM, 2), 256>>>();
    lse_kernel<<<BSZ, 256>>>();
    pm_partial_kernel<<<dim3(BSZ / TI, JCHUNKS), 256>>>(latent);
    pm_log_kernel<<<BSZ, 256>>>();
    final_kernel<<<1, 256>>>((float*)d_out);
}

// round 4
// speedup vs baseline: 3.0661x; 1.4994x over previous
#include <cuda_runtime.h>
#include <math.h>
#include <stdint.h>

#define BSZ 512
#define ZD  256
#define KK2 512                 // concat K for GEMM (h|s vs w|a)
#define REC_BLOCKS 1024
#define TI 16                   // i-values per pm block
#define JCHUNKS 16
#define JC (BSZ / JCHUNKS)      // 32
#define SPLITK 8
#define KSP (KK2 / SPLITK)      // 64
#define GBK 32
#define LOG2PI_F 1.8378770664093453f
#define LOG2E_F  1.4426950408889634f

typedef unsigned long long u64;

// ---------------- scratch ----------------------------------------------------
__device__ float g_wa[BSZ * KK2];     // [j][0:256)=w=exp(lv), [256:512)=a=mu*w
__device__ float g_hs[BSZ * KK2];     // [i][0:256)=-0.5*lat^2, [256:512)=lat
__device__ float g_w2[BSZ * ZD];      // w * log2e    (pm)
__device__ float g_a2[BSZ * ZD];      // a * log2e    (pm)
__device__ float g_c2[BSZ * ZD];      // c * log2e    (pm)
__device__ float g_Crow[BSZ];
__device__ float g_dwkl[BSZ];
__device__ float g_recb[REC_BLOCKS];
__device__ float g_logqz[BSZ];
__device__ float g_pm[BSZ];
__device__ float g_log_norm;
__device__ float g_M[SPLITK][BSZ * BSZ];     // GEMM split-K partials (8MB)
__device__ float g_S[JCHUNKS][BSZ * ZD];     // pm partial sums (8MB)

// ---------------- packed f32x2 helpers ---------------------------------------
__device__ __forceinline__ u64 pk2(float lo, float hi) {
    u64 r; asm("mov.b64 %0,{%1,%2};" : "=l"(r) : "f"(lo), "f"(hi)); return r;
}
__device__ __forceinline__ void upk2(u64 v, float& lo, float& hi) {
    asm("mov.b64 {%0,%1},%2;" : "=f"(lo), "=f"(hi) : "l"(v));
}
__device__ __forceinline__ u64 fma2(u64 a, u64 b, u64 c) {
    u64 d; asm("fma.rn.f32x2 %0,%1,%2,%3;" : "=l"(d) : "l"(a), "l"(b), "l"(c)); return d;
}
__device__ __forceinline__ u64 add2(u64 a, u64 b) {
    u64 d; asm("add.rn.f32x2 %0,%1,%2;" : "=l"(d) : "l"(a), "l"(b)); return d;
}
__device__ __forceinline__ u64 mul2(u64 a, u64 b) {
    u64 d; asm("mul.rn.f32x2 %0,%1,%2;" : "=l"(d) : "l"(a), "l"(b)); return d;
}
__device__ __forceinline__ float ex2f(float x) {
    float y; asm("ex2.approx.f32 %0,%1;" : "=f"(y) : "f"(x)); return y;
}

// ---------------- reductions --------------------------------------------------
__device__ __forceinline__ float warp_sum(float v) {
#pragma unroll
    for (int o = 16; o; o >>= 1) v += __shfl_xor_sync(0xffffffffu, v, o);
    return v;
}
__device__ __forceinline__ float warp_max(float v) {
#pragma unroll
    for (int o = 16; o; o >>= 1) v = fmaxf(v, __shfl_xor_sync(0xffffffffu, v, o));
    return v;
}
__device__ __forceinline__ float block_sum_256(float v, float* sh) {
    int lane = threadIdx.x & 31, w = threadIdx.x >> 5;
    v = warp_sum(v);
    if (lane == 0) sh[w] = v;
    __syncthreads();
    float r = (threadIdx.x < 8) ? sh[threadIdx.x] : 0.0f;
    if (w == 0) r = warp_sum(r);
    __syncthreads();
    return r;
}
__device__ __forceinline__ float block_max_256(float v, float* sh) {
    int lane = threadIdx.x & 31, w = threadIdx.x >> 5;
    v = warp_max(v);
    if (lane == 0) sh[w] = v;
    __syncthreads();
    float r = (threadIdx.x < 8) ? sh[threadIdx.x] : -INFINITY;
    if (w == 0) r = warp_max(r);
    __syncthreads();
    return r;
}

// ---------------- FMA-pipe natural log (used only in pm_log) -------------------
__device__ __forceinline__ float fast_log(float x) {
    int ix = __float_as_int(x);
    int e  = (ix - 0x3f3504f3) >> 23;
    float m = __int_as_float(ix - (e << 23));
    float f = m - 1.0f;
    float z = f * f;
    float y = 7.0376836292e-2f;
    y = fmaf(y, f, -1.1514610310e-1f);
    y = fmaf(y, f,  1.1676998740e-1f);
    y = fmaf(y, f, -1.2420140846e-1f);
    y = fmaf(y, f,  1.4249322787e-1f);
    y = fmaf(y, f, -1.6668057665e-1f);
    y = fmaf(y, f,  2.0000714765e-1f);
    y = fmaf(y, f, -2.4999993993e-1f);
    y = fmaf(y, f,  3.3333331174e-1f);
    y = y * f * z;
    float ef = (float)e;
    y = fmaf(ef, -2.12194440e-4f, y);
    y = fmaf(-0.5f, z, y);
    float r = f + y;
    return fmaf(ef, 0.693359375f, r);
}

// ---------------- kernel 1: precompute ----------------------------------------
__global__ void __launch_bounds__(256) prep_kernel(const float* __restrict__ mu,
                                                   const float* __restrict__ logvar,
                                                   const void* __restrict__ dsz) {
    __shared__ float sh[8];
    __shared__ float sh2[8];
    int j = blockIdx.x;
    int t = threadIdx.x;
    int idx = j * ZD + t;

    float lv = logvar[idx];
    float m  = mu[idx];
    float w  = __expf(lv);
    float a  = m * w;
    float c  = -0.5f * (fmaf(m * m, w, lv) + LOG2PI_F);
    g_wa[j * KK2 + t]      = w;
    g_wa[j * KK2 + ZD + t] = a;
    g_w2[idx] = w * LOG2E_F;
    g_a2[idx] = a * LOG2E_F;
    g_c2[idx] = c * LOG2E_F;

    float dw = fmaf(0.5f, __expf(lv + m * m), fmaf(-0.5f, lv, -0.5f));

    int lane = t & 31, wp = t >> 5;
    float cs = warp_sum(c);
    float ds = warp_sum(dw);
    if (lane == 0) { sh[wp] = cs; sh2[wp] = ds; }
    __syncthreads();
    if (t == 0) {
        float ct = 0.0f, dt = 0.0f;
#pragma unroll
        for (int q = 0; q < 8; q++) { ct += sh[q]; dt += sh2[q]; }
        g_Crow[j] = ct;
        g_dwkl[j] = dt;
    }

    if (j == 0 && t == 0) {
        int   iv = ((const int*)dsz)[0];
        float fv = ((const float*)dsz)[0];
        float ds_val = (iv > 0 && iv < 1073741824) ? (float)iv : fv;
        g_log_norm = logf((float)BSZ) + logf(ds_val);
    }
}

// ---------------- kernel 1b: latent features for GEMM --------------------------
__global__ void __launch_bounds__(256) lat_prep_kernel(const float* __restrict__ lat) {
    int i = blockIdx.x, t = threadIdx.x;
    float v = lat[i * ZD + t];
    g_hs[i * KK2 + t]      = -0.5f * v * v;
    g_hs[i * KK2 + ZD + t] = v;
}

// ---------------- kernel 2: BCE reduction (MUFU log, float4) -------------------
__global__ void __launch_bounds__(256) rec_kernel(const float* __restrict__ data,
                                                  const float* __restrict__ recon,
                                                  int n4) {
    __shared__ float sh[8];
    const float4* d4 = (const float4*)data;
    const float4* r4 = (const float4*)recon;
    float acc = 0.0f;
    for (int i = blockIdx.x * blockDim.x + threadIdx.x; i < n4;
         i += gridDim.x * blockDim.x) {
        float4 d = d4[i];
        float4 r = r4[i];
        acc += d.x * __logf(r.x) + (1.0f - d.x) * __logf(1.0f - r.x);
        acc += d.y * __logf(r.y) + (1.0f - d.y) * __logf(1.0f - r.y);
        acc += d.z * __logf(r.z) + (1.0f - d.z) * __logf(1.0f - r.z);
        acc += d.w * __logf(r.w) + (1.0f - d.w) * __logf(1.0f - r.w);
    }
    float s = block_sum_256(acc, sh);
    if (threadIdx.x == 0) g_recb[blockIdx.x] = s;
}

// ---------------- kernel 3a: tiled GEMM, split-K=8 ------------------------------
// M_split[z][i][j] = sum_{k in split z} g_hs[i][k] * g_wa[j][k]
__global__ void __launch_bounds__(256) gemm_kernel() {
    __shared__ float As[GBK * 68];
    __shared__ float Bs[GBK * 68];
    int tid = threadIdx.x;
    int j0 = blockIdx.x * 64;
    int i0 = blockIdx.y * 64;
    int kb = blockIdx.z * KSP;
    int tx = tid & 15, ty = tid >> 4;

    float acc[4][4];
#pragma unroll
    for (int r = 0; r < 4; r++)
#pragma unroll
        for (int c = 0; c < 4; c++) acc[r][c] = 0.0f;

#pragma unroll
    for (int kc = 0; kc < KSP; kc += GBK) {
#pragma unroll
        for (int p = 0; p < 2; p++) {
            int q   = tid + p * 256;
            int row = q >> 3;
            int k4  = (q & 7) * 4;
            float4 va = *(const float4*)&g_hs[(i0 + row) * KK2 + kb + kc + k4];
            float4 vb = *(const float4*)&g_wa[(j0 + row) * KK2 + kb + kc + k4];
            As[(k4 + 0) * 68 + row] = va.x;
            As[(k4 + 1) * 68 + row] = va.y;
            As[(k4 + 2) * 68 + row] = va.z;
            As[(k4 + 3) * 68 + row] = va.w;
            Bs[(k4 + 0) * 68 + row] = vb.x;
            Bs[(k4 + 1) * 68 + row] = vb.y;
            Bs[(k4 + 2) * 68 + row] = vb.z;
            Bs[(k4 + 3) * 68 + row] = vb.w;
        }
        __syncthreads();
#pragma unroll 8
        for (int kk = 0; kk < GBK; kk++) {
            float4 av = *(const float4*)&As[kk * 68 + ty * 4];
            float4 bv = *(const float4*)&Bs[kk * 68 + tx * 4];
            acc[0][0] = fmaf(av.x, bv.x, acc[0][0]);
            acc[0][1] = fmaf(av.x, bv.y, acc[0][1]);
            acc[0][2] = fmaf(av.x, bv.z, acc[0][2]);
            acc[0][3] = fmaf(av.x, bv.w, acc[0][3]);
            acc[1][0] = fmaf(av.y, bv.x, acc[1][0]);
            acc[1][1] = fmaf(av.y, bv.y, acc[1][1]);
            acc[1][2] = fmaf(av.y, bv.z, acc[1][2]);
            acc[1][3] = fmaf(av.y, bv.w, acc[1][3]);
            acc[2][0] = fmaf(av.z, bv.x, acc[2][0]);
            acc[2][1] = fmaf(av.z, bv.y, acc[2][1]);
            acc[2][2] = fmaf(av.z, bv.z, acc[2][2]);
            acc[2][3] = fmaf(av.z, bv.w, acc[2][3]);
            acc[3][0] = fmaf(av.w, bv.x, acc[3][0]);
            acc[3][1] = fmaf(av.w, bv.y, acc[3][1]);
            acc[3][2] = fmaf(av.w, bv.z, acc[3][2]);
            acc[3][3] = fmaf(av.w, bv.w, acc[3][3]);
        }
        __syncthreads();
    }

    float* out = g_M[blockIdx.z];
#pragma unroll
    for (int r = 0; r < 4; r++) {
        float4 v = make_float4(acc[r][0], acc[r][1], acc[r][2], acc[r][3]);
        *(float4*)&out[(i0 + ty * 4 + r) * BSZ + j0 + tx * 4] = v;
    }
}

// ---------------- kernel 3b: LSE over rows of M ---------------------------------
__global__ void __launch_bounds__(256) lse_kernel() {
    __shared__ float sh[8];
    __shared__ float smx;
    int i = blockIdx.x, t = threadIdx.x;

    float v0 = g_Crow[t];
    float v1 = g_Crow[t + 256];
#pragma unroll
    for (int z = 0; z < SPLITK; z++) {
        v0 += g_M[z][i * BSZ + t];
        v1 += g_M[z][i * BSZ + t + 256];
    }

    float mx = block_max_256(fmaxf(v0, v1), sh);
    if (t == 0) smx = mx;
    __syncthreads();
    mx = smx;

    float se = __expf(v0 - mx) + __expf(v1 - mx);
    se = block_sum_256(se, sh);
    if (t == 0) g_logqz[i] = mx + __logf(se) - g_log_norm;
}

// ---------------- kernel 4: pm partial sums (f32x2 + MUFU hybrid) ---------------
// grid (BSZ/TI, JCHUNKS). Thread t owns k=t for TI=16 i-values (8 pairs).
// Pair 0 uses the FMA-pipe exp2 polynomial; pairs 1..7 use MUFU ex2.approx,
// so both pipes run in parallel.
__global__ void __launch_bounds__(256) pm_partial_kernel(const float* __restrict__ lat) {
    int i0 = blockIdx.x * TI;
    int jc = blockIdx.y;
    int t  = threadIdx.x;

    u64 s2[TI / 2], h2[TI / 2], acc[TI / 2];
#pragma unroll
    for (int p = 0; p < TI / 2; p++) {
        float v0 = lat[(i0 + 2 * p) * ZD + t];
        float v1 = lat[(i0 + 2 * p + 1) * ZD + t];
        s2[p]  = pk2(v0 * LOG2E_F, v1 * LOG2E_F);
        h2[p]  = pk2(-0.5f * v0 * v0, -0.5f * v1 * v1);
        acc[p] = 0ULL;
    }

    const float* wp = g_w2 + jc * JC * ZD + t;
    const float* ap = g_a2 + jc * JC * ZD + t;
    const float* cp = g_c2 + jc * JC * ZD + t;

    const u64 MAGIC2  = pk2( 12582912.0f,  12582912.0f);
    const u64 NMAGIC2 = pk2(-12582912.0f, -12582912.0f);
    const u64 NEG1    = pk2(-1.0f, -1.0f);
    const u64 C0 = pk2(1.0f, 1.0f);
    const u64 C1 = pk2(0.69314718f,  0.69314718f);
    const u64 C2 = pk2(0.24022650f,  0.24022650f);
    const u64 C3 = pk2(0.055504110f, 0.055504110f);
    const u64 C4 = pk2(0.0096181291f, 0.0096181291f);
    const u64 C5 = pk2(0.0013333558f, 0.0013333558f);

#pragma unroll 2
    for (int j = 0; j < JC; j++) {
        float w = wp[j * ZD];
        float a = ap[j * ZD];
        float c = cp[j * ZD];
        u64 w2 = pk2(w, w), a2 = pk2(a, a), c2 = pk2(c, c);

        // pair 0: FMA-pipe polynomial exp2
        {
            u64 x  = fma2(h2[0], w2, fma2(s2[0], a2, c2));
            u64 tt = add2(x, MAGIC2);
            u64 tm = add2(tt, NMAGIC2);
            u64 r  = fma2(tm, NEG1, x);
            u64 rr = mul2(r, r);
            u64 A  = fma2(r, C1, C0);
            u64 B  = fma2(r, C3, C2);
            u64 Cc = fma2(r, C5, C4);
            u64 D  = fma2(rr, Cc, B);
            u64 E  = fma2(rr, D, A);
            int tlo = (int)tt;
            int thi = (int)(tt >> 32);
            float nlo = __int_as_float((tlo << 23) + 0x3F800000);
            float nhi = __int_as_float((thi << 23) + 0x3F800000);
            acc[0] = fma2(E, pk2(nlo, nhi), acc[0]);
        }
        // pairs 1..7: MUFU ex2
#pragma unroll
        for (int p = 1; p < TI / 2; p++) {
            u64 x = fma2(h2[p], w2, fma2(s2[p], a2, c2));
            float xlo, xhi;
            upk2(x, xlo, xhi);
            float elo = ex2f(xlo);
            float ehi = ex2f(xhi);
            acc[p] = add2(acc[p], pk2(elo, ehi));
        }
    }

#pragma unroll
    for (int p = 0; p < TI / 2; p++) {
        float a0, a1;
        upk2(acc[p], a0, a1);
        g_S[jc][(i0 + 2 * p) * ZD + t]     = a0;
        g_S[jc][(i0 + 2 * p + 1) * ZD + t] = a1;
    }
}

// ---------------- kernel 5: pm finalize ------------------------------------------
__global__ void __launch_bounds__(256) pm_log_kernel() {
    __shared__ float sh[8];
    int i = blockIdx.x;
    int t = threadIdx.x;
    int idx = i * ZD + t;

    float S = 0.0f;
#pragma unroll
    for (int jc = 0; jc < JCHUNKS; jc++) S += g_S[jc][idx];
    float v = fast_log(S);

    float tot = block_sum_256(v, sh);
    if (t == 0) g_pm[i] = tot - (float)ZD * g_log_norm;
}

// ---------------- kernel 6: finalize ----------------------------------------------
__global__ void __launch_bounds__(256) final_kernel(float* __restrict__ out) {
    __shared__ float sh[8];
    int t = threadIdx.x;

    float rec = 0.0f;
    for (int b = t; b < REC_BLOCKS; b += 256) rec += g_recb[b];
    float dw = 0.0f, tc = 0.0f;
    for (int b = t; b < BSZ; b += 256) {
        dw += g_dwkl[b];
        tc += g_logqz[b] - g_pm[b];
    }

    rec = block_sum_256(rec, sh);
    dw  = block_sum_256(dw,  sh);
    tc  = block_sum_256(tc,  sh);

    if (t == 0) out[0] = (tc + dw - rec) * (1.0f / (float)BSZ);
}

// ---------------- launch ------------------------------------------------------------
extern "C" void kernel_launch(void* const* d_in, const int* in_sizes, int n_in,
                              void* d_out, int out_size) {
    const float* data   = (const float*)d_in[0];
    const float* recon  = (const float*)d_in[1];
    const float* latent = (const float*)d_in[2];
    const float* mu     = (const float*)d_in[3];
    const float* logvar = (const float*)d_in[4];
    const void*  dsz    = d_in[5];

    int npix = in_sizes[0];

    prep_kernel<<<BSZ, 256>>>(mu, logvar, dsz);
    lat_prep_kernel<<<BSZ, 256>>>(latent);
    rec_kernel<<<REC_BLOCKS, 256>>>(data, recon, npix / 4);
    gemm_kernel<<<dim3(BSZ / 64, BSZ / 64, SPLITK), 256>>>();
    lse_kernel<<<BSZ, 256>>>();
    pm_partial_kernel<<<dim3(BSZ / TI, JCHUNKS), 256>>>(latent);
    pm_log_kernel<<<BSZ, 256>>>();
    final_kernel<<<1, 256>>>((float*)d_out);
}

// round 5
// speedup vs baseline: 3.4000x; 1.1089x over previous
#include <cuda_runtime.h>
#include <math.h>
#include <stdint.h>

#define BSZ 512
#define ZD  256
#define KK2 512                 // concat K for GEMM (h|s vs w|a)
#define REC_BLOCKS 512
#define TI 16                   // i-values per pm block
#define JCHUNKS 16
#define JC (BSZ / JCHUNKS)      // 32
#define SPLITK 8
#define KSP (KK2 / SPLITK)      // 64
#define GBK 32
#define LOG2PI_F 1.8378770664093453f
#define LOG2E_F  1.4426950408889634f

typedef unsigned long long u64;

// ---------------- scratch ----------------------------------------------------
__device__ float g_wa[BSZ * KK2];     // [j][0:256)=w=exp(lv), [256:512)=a=mu*w
__device__ float g_hs[BSZ * KK2];     // [i][0:256)=-0.5*lat^2, [256:512)=lat
__device__ float g_w2[BSZ * ZD];      // w * log2e    (pm)
__device__ float g_a2[BSZ * ZD];      // a * log2e    (pm)
__device__ float g_c2[BSZ * ZD];      // c * log2e    (pm)
__device__ float g_Crow[BSZ];
__device__ float g_dwkl[BSZ];
__device__ float g_recb[REC_BLOCKS];
__device__ float g_tc[BSZ];
__device__ float g_log_norm;
__device__ unsigned int g_ctr;
__device__ float g_M[SPLITK][BSZ * BSZ];     // GEMM split-K partials (8MB)
__device__ float g_S[JCHUNKS][BSZ * ZD];     // pm partial sums (8MB)

// ---------------- packed f32x2 helpers ---------------------------------------
__device__ __forceinline__ u64 pk2(float lo, float hi) {
    u64 r; asm("mov.b64 %0,{%1,%2};" : "=l"(r) : "f"(lo), "f"(hi)); return r;
}
__device__ __forceinline__ void upk2(u64 v, float& lo, float& hi) {
    asm("mov.b64 {%0,%1},%2;" : "=f"(lo), "=f"(hi) : "l"(v));
}
__device__ __forceinline__ u64 fma2(u64 a, u64 b, u64 c) {
    u64 d; asm("fma.rn.f32x2 %0,%1,%2,%3;" : "=l"(d) : "l"(a), "l"(b), "l"(c)); return d;
}
__device__ __forceinline__ u64 add2(u64 a, u64 b) {
    u64 d; asm("add.rn.f32x2 %0,%1,%2;" : "=l"(d) : "l"(a), "l"(b)); return d;
}
__device__ __forceinline__ u64 mul2(u64 a, u64 b) {
    u64 d; asm("mul.rn.f32x2 %0,%1,%2;" : "=l"(d) : "l"(a), "l"(b)); return d;
}
__device__ __forceinline__ float ex2f(float x) {
    float y; asm("ex2.approx.f32 %0,%1;" : "=f"(y) : "f"(x)); return y;
}

// ---------------- reductions --------------------------------------------------
__device__ __forceinline__ float warp_sum(float v) {
#pragma unroll
    for (int o = 16; o; o >>= 1) v += __shfl_xor_sync(0xffffffffu, v, o);
    return v;
}
__device__ __forceinline__ float warp_max(float v) {
#pragma unroll
    for (int o = 16; o; o >>= 1) v = fmaxf(v, __shfl_xor_sync(0xffffffffu, v, o));
    return v;
}
__device__ __forceinline__ float block_sum_256(float v, float* sh) {
    int lane = threadIdx.x & 31, w = threadIdx.x >> 5;
    v = warp_sum(v);
    if (lane == 0) sh[w] = v;
    __syncthreads();
    float r = (threadIdx.x < 8) ? sh[threadIdx.x] : 0.0f;
    if (w == 0) r = warp_sum(r);
    __syncthreads();
    return r;
}
__device__ __forceinline__ float block_max_256(float v, float* sh) {
    int lane = threadIdx.x & 31, w = threadIdx.x >> 5;
    v = warp_max(v);
    if (lane == 0) sh[w] = v;
    __syncthreads();
    float r = (threadIdx.x < 8) ? sh[threadIdx.x] : -INFINITY;
    if (w == 0) r = warp_max(r);
    __syncthreads();
    return r;
}

// ---------------- FMA-pipe natural log -----------------------------------------
__device__ __forceinline__ float fast_log(float x) {
    int ix = __float_as_int(x);
    int e  = (ix - 0x3f3504f3) >> 23;
    float m = __int_as_float(ix - (e << 23));
    float f = m - 1.0f;
    float z = f * f;
    float y = 7.0376836292e-2f;
    y = fmaf(y, f, -1.1514610310e-1f);
    y = fmaf(y, f,  1.1676998740e-1f);
    y = fmaf(y, f, -1.2420140846e-1f);
    y = fmaf(y, f,  1.4249322787e-1f);
    y = fmaf(y, f, -1.6668057665e-1f);
    y = fmaf(y, f,  2.0000714765e-1f);
    y = fmaf(y, f, -2.4999993993e-1f);
    y = fmaf(y, f,  3.3333331174e-1f);
    y = y * f * z;
    float ef = (float)e;
    y = fmaf(ef, -2.12194440e-4f, y);
    y = fmaf(-0.5f, z, y);
    float r = f + y;
    return fmaf(ef, 0.693359375f, r);
}

// ================= kernel 1: fused precompute ===================================
__global__ void __launch_bounds__(256) prep_kernel(const float* __restrict__ mu,
                                                   const float* __restrict__ logvar,
                                                   const float* __restrict__ lat,
                                                   const void* __restrict__ dsz) {
    __shared__ float sh[8];
    __shared__ float sh2[8];
    int j = blockIdx.x;
    int t = threadIdx.x;
    int idx = j * ZD + t;

    float lv = logvar[idx];
    float m  = mu[idx];
    float w  = __expf(lv);
    float a  = m * w;
    float c  = -0.5f * (fmaf(m * m, w, lv) + LOG2PI_F);
    g_wa[j * KK2 + t]      = w;
    g_wa[j * KK2 + ZD + t] = a;
    g_w2[idx] = w * LOG2E_F;
    g_a2[idx] = a * LOG2E_F;
    g_c2[idx] = c * LOG2E_F;

    float v = lat[idx];
    g_hs[j * KK2 + t]      = -0.5f * v * v;
    g_hs[j * KK2 + ZD + t] = v;

    float dw = fmaf(0.5f, __expf(lv + m * m), fmaf(-0.5f, lv, -0.5f));

    int lane = t & 31, wp = t >> 5;
    float cs = warp_sum(c);
    float ds = warp_sum(dw);
    if (lane == 0) { sh[wp] = cs; sh2[wp] = ds; }
    __syncthreads();
    if (t == 0) {
        float ct = 0.0f, dt = 0.0f;
#pragma unroll
        for (int q = 0; q < 8; q++) { ct += sh[q]; dt += sh2[q]; }
        g_Crow[j] = ct;
        g_dwkl[j] = dt;
    }

    if (j == 0 && t == 0) {
        int   iv = ((const int*)dsz)[0];
        float fv = ((const float*)dsz)[0];
        float ds_val = (iv > 0 && iv < 1073741824) ? (float)iv : fv;
        g_log_norm = logf((float)BSZ) + logf(ds_val);
        g_ctr = 0;
    }
}

// ================= mega-kernel bodies ===========================================
__device__ void gemm_body(int idx, float* As, float* Bs) {
    int tid = threadIdx.x;
    int kb  = (idx >> 6) * KSP;
    int rem = idx & 63;
    int j0  = (rem & 7) * 64;
    int i0  = (rem >> 3) * 64;
    int tx = tid & 15, ty = tid >> 4;

    float acc[4][4];
#pragma unroll
    for (int r = 0; r < 4; r++)
#pragma unroll
        for (int c = 0; c < 4; c++) acc[r][c] = 0.0f;

#pragma unroll
    for (int kc = 0; kc < KSP; kc += GBK) {
#pragma unroll
        for (int p = 0; p < 2; p++) {
            int q   = tid + p * 256;
            int row = q >> 3;
            int k4  = (q & 7) * 4;
            float4 va = *(const float4*)&g_hs[(i0 + row) * KK2 + kb + kc + k4];
            float4 vb = *(const float4*)&g_wa[(j0 + row) * KK2 + kb + kc + k4];
            As[(k4 + 0) * 68 + row] = va.x;
            As[(k4 + 1) * 68 + row] = va.y;
            As[(k4 + 2) * 68 + row] = va.z;
            As[(k4 + 3) * 68 + row] = va.w;
            Bs[(k4 + 0) * 68 + row] = vb.x;
            Bs[(k4 + 1) * 68 + row] = vb.y;
            Bs[(k4 + 2) * 68 + row] = vb.z;
            Bs[(k4 + 3) * 68 + row] = vb.w;
        }
        __syncthreads();
#pragma unroll 8
        for (int kk = 0; kk < GBK; kk++) {
            float4 av = *(const float4*)&As[kk * 68 + ty * 4];
            float4 bv = *(const float4*)&Bs[kk * 68 + tx * 4];
            acc[0][0] = fmaf(av.x, bv.x, acc[0][0]);
            acc[0][1] = fmaf(av.x, bv.y, acc[0][1]);
            acc[0][2] = fmaf(av.x, bv.z, acc[0][2]);
            acc[0][3] = fmaf(av.x, bv.w, acc[0][3]);
            acc[1][0] = fmaf(av.y, bv.x, acc[1][0]);
            acc[1][1] = fmaf(av.y, bv.y, acc[1][1]);
            acc[1][2] = fmaf(av.y, bv.z, acc[1][2]);
            acc[1][3] = fmaf(av.y, bv.w, acc[1][3]);
            acc[2][0] = fmaf(av.z, bv.x, acc[2][0]);
            acc[2][1] = fmaf(av.z, bv.y, acc[2][1]);
            acc[2][2] = fmaf(av.z, bv.z, acc[2][2]);
            acc[2][3] = fmaf(av.z, bv.w, acc[2][3]);
            acc[3][0] = fmaf(av.w, bv.x, acc[3][0]);
            acc[3][1] = fmaf(av.w, bv.y, acc[3][1]);
            acc[3][2] = fmaf(av.w, bv.z, acc[3][2]);
            acc[3][3] = fmaf(av.w, bv.w, acc[3][3]);
        }
        __syncthreads();
    }

    float* out = g_M[idx >> 6];
#pragma unroll
    for (int r = 0; r < 4; r++) {
        float4 v = make_float4(acc[r][0], acc[r][1], acc[r][2], acc[r][3]);
        *(float4*)&out[(i0 + ty * 4 + r) * BSZ + j0 + tx * 4] = v;
    }
}

__device__ void pm_body(int idx, const float* __restrict__ lat) {
    int jc = idx & (JCHUNKS - 1);
    int i0 = (idx >> 4) * TI;
    int t  = threadIdx.x;

    u64 s2[TI / 2], h2[TI / 2], acc[TI / 2];
#pragma unroll
    for (int p = 0; p < TI / 2; p++) {
        float v0 = lat[(i0 + 2 * p) * ZD + t];
        float v1 = lat[(i0 + 2 * p + 1) * ZD + t];
        s2[p]  = pk2(v0 * LOG2E_F, v1 * LOG2E_F);
        h2[p]  = pk2(-0.5f * v0 * v0, -0.5f * v1 * v1);
        acc[p] = 0ULL;
    }

    const float* wp = g_w2 + jc * JC * ZD + t;
    const float* ap = g_a2 + jc * JC * ZD + t;
    const float* cp = g_c2 + jc * JC * ZD + t;

    const u64 MAGIC2  = pk2( 12582912.0f,  12582912.0f);
    const u64 NMAGIC2 = pk2(-12582912.0f, -12582912.0f);
    const u64 NEG1    = pk2(-1.0f, -1.0f);
    const u64 C0 = pk2(1.0f, 1.0f);
    const u64 C1 = pk2(0.69314718f,  0.69314718f);
    const u64 C2 = pk2(0.24022650f,  0.24022650f);
    const u64 C3 = pk2(0.055504110f, 0.055504110f);
    const u64 C4 = pk2(0.0096181291f, 0.0096181291f);
    const u64 C5 = pk2(0.0013333558f, 0.0013333558f);

#pragma unroll 2
    for (int j = 0; j < JC; j++) {
        float w = wp[j * ZD];
        float a = ap[j * ZD];
        float c = cp[j * ZD];
        u64 w2 = pk2(w, w), a2 = pk2(a, a), c2 = pk2(c, c);

        // pair 0: FMA-pipe polynomial exp2 (keeps fma pipe fed while MUFU drains)
        {
            u64 x  = fma2(h2[0], w2, fma2(s2[0], a2, c2));
            u64 tt = add2(x, MAGIC2);
            u64 tm = add2(tt, NMAGIC2);
            u64 r  = fma2(tm, NEG1, x);
            u64 rr = mul2(r, r);
            u64 A  = fma2(r, C1, C0);
            u64 B  = fma2(r, C3, C2);
            u64 Cc = fma2(r, C5, C4);
            u64 D  = fma2(rr, Cc, B);
            u64 E  = fma2(rr, D, A);
            int tlo = (int)tt;
            int thi = (int)(tt >> 32);
            float nlo = __int_as_float((tlo << 23) + 0x3F800000);
            float nhi = __int_as_float((thi << 23) + 0x3F800000);
            acc[0] = fma2(E, pk2(nlo, nhi), acc[0]);
        }
        // pairs 1..7: MUFU ex2
#pragma unroll
        for (int p = 1; p < TI / 2; p++) {
            u64 x = fma2(h2[p], w2, fma2(s2[p], a2, c2));
            float xlo, xhi;
            upk2(x, xlo, xhi);
            float elo = ex2f(xlo);
            float ehi = ex2f(xhi);
            acc[p] = add2(acc[p], pk2(elo, ehi));
        }
    }

#pragma unroll
    for (int p = 0; p < TI / 2; p++) {
        float a0, a1;
        upk2(acc[p], a0, a1);
        g_S[jc][(i0 + 2 * p) * ZD + t]     = a0;
        g_S[jc][(i0 + 2 * p + 1) * ZD + t] = a1;
    }
}

__device__ void rec_body(int idx, const float* __restrict__ data,
                         const float* __restrict__ recon, int n4, float* sh) {
    const float4* d4 = (const float4*)data;
    const float4* r4 = (const float4*)recon;
    float acc = 0.0f;
    for (int i = idx * 256 + threadIdx.x; i < n4; i += REC_BLOCKS * 256) {
        float4 d = d4[i];
        float4 r = r4[i];
        acc += d.x * __logf(r.x) + (1.0f - d.x) * __logf(1.0f - r.x);
        acc += d.y * __logf(r.y) + (1.0f - d.y) * __logf(1.0f - r.y);
        acc += d.z * __logf(r.z) + (1.0f - d.z) * __logf(1.0f - r.z);
        acc += d.w * __logf(r.w) + (1.0f - d.w) * __logf(1.0f - r.w);
    }
    float s = block_sum_256(acc, sh);
    if (threadIdx.x == 0) g_recb[idx] = s;
}

// ================= kernel 2: heterogeneous mega-kernel ===========================
// 1536 blocks; type = bx % 3 interleaves gemm / pm / rec across every wave so
// the FMA pipe (gemm + pm poly), MUFU (pm ex2 + rec log) and DRAM (rec) overlap.
__global__ void __launch_bounds__(256, 3) mega_kernel(const float* __restrict__ data,
                                                      const float* __restrict__ recon,
                                                      const float* __restrict__ lat,
                                                      int n4) {
    __shared__ float smem[2 * GBK * 68];
    int bx = blockIdx.x;
    int type = bx % 3;
    int idx  = bx / 3;
    if (type == 0) {
        gemm_body(idx, smem, smem + GBK * 68);
    } else if (type == 1) {
        pm_body(idx, lat);
    } else {
        rec_body(idx, data, recon, n4, smem);
    }
}

// ================= kernel 3: epilogue (lse + pm_log + last-block final) ==========
__global__ void __launch_bounds__(256) epi_kernel(float* __restrict__ out) {
    __shared__ float sh[8];
    __shared__ float smx;
    __shared__ bool s_last;
    int i = blockIdx.x, t = threadIdx.x;

    // --- logqz: LSE over j of row-sum matrix ---
    float v0 = g_Crow[t];
    float v1 = g_Crow[t + 256];
#pragma unroll
    for (int z = 0; z < SPLITK; z++) {
        v0 += g_M[z][i * BSZ + t];
        v1 += g_M[z][i * BSZ + t + 256];
    }
    float mx = block_max_256(fmaxf(v0, v1), sh);
    if (t == 0) smx = mx;
    __syncthreads();
    mx = smx;
    float se = __expf(v0 - mx) + __expf(v1 - mx);
    se = block_sum_256(se, sh);
    float logqz = mx + __logf(se) - g_log_norm;   // valid in t==0

    // --- pm: sum_k log(sum over chunks) ---
    int idx = i * ZD + t;
    float S = 0.0f;
#pragma unroll
    for (int jc = 0; jc < JCHUNKS; jc++) S += g_S[jc][idx];
    float v = fast_log(S);
    float tot = block_sum_256(v, sh);

    if (t == 0) {
        float pm = tot - (float)ZD * g_log_norm;
        g_tc[i] = logqz - pm;
        __threadfence();
        unsigned int prev = atomicAdd(&g_ctr, 1u);
        s_last = (prev == BSZ - 1);
    }
    __syncthreads();

    if (s_last) {
        float rec = 0.0f;
        for (int b = t; b < REC_BLOCKS; b += 256) rec += g_recb[b];
        float dw = 0.0f, tc = 0.0f;
        for (int b = t; b < BSZ; b += 256) {
            dw += g_dwkl[b];
            tc += g_tc[b];
        }
        rec = block_sum_256(rec, sh);
        dw  = block_sum_256(dw,  sh);
        tc  = block_sum_256(tc,  sh);
        if (t == 0) out[0] = (tc + dw - rec) * (1.0f / (float)BSZ);
    }
}

// ---------------- launch ----------------------------------------------------------
extern "C" void kernel_launch(void* const* d_in, const int* in_sizes, int n_in,
                              void* d_out, int out_size) {
    const float* data   = (const float*)d_in[0];
    const float* recon  = (const float*)d_in[1];
    const float* latent = (const float*)d_in[2];
    const float* mu     = (const float*)d_in[3];
    const float* logvar = (const float*)d_in[4];
    const void*  dsz    = d_in[5];

    int n4 = in_sizes[0] / 4;

    prep_kernel<<<BSZ, 256>>>(mu, logvar, latent, dsz);
    mega_kernel<<<1536, 256>>>(data, recon, latent, n4);
    epi_kernel<<<BSZ, 256>>>((float*)d_out);
}